// round 14
// baseline (speedup 1.0000x reference)
#include <cuda_runtime.h>
#include <math.h>

#define NBLK 128
#define NTHR 256
#define HID  128
#define BINS 513
#define WIN  1024
#define ENCN 256

// ---------------- tagged scratch: payload carries the ready-flag ----------------
__device__ __align__(16) float2 g_h1t[HID], g_h2t[HID], g_h1bt[HID];
__device__ __align__(16) float4 g_spect[BINS];        // {re, im, tag, 0}
__device__ __align__(16) float2 g_encPt[32*ENCN];     // partial enc rows, tagged
__device__ __align__(16) float2 g_enct[ENCN];         // summed enc, tagged (CTA32)
__device__ __align__(16) float2 g_d2Pt[16*ENCN];      // dense2 partial dots, tagged
__device__ unsigned g_epoch;                          // bumped by CTA0 at end

// ---------------- dynamic smem layout (bytes) ----------------
#define OFF_ENCWT 0                   // 32 × 257 floats = 32896
#define OFF_Y1S   32896               // 32 floats
#define OFF_EST   33024               // 256 floats
#define OFF_RED   34048               // 8 floats
#define OFF_RED2  34080               // 8 floats
#define OFF_ENCN  34112               // 256 floats
#define OFF_H2LOC 35136               // 8 floats
#define SMEM_TOTAL 35200

__device__ __forceinline__ float sigm(float x){ return 1.0f/(1.0f+__expf(-x)); }

__device__ __forceinline__ float wsum(float v){
#pragma unroll
    for (int o = 16; o > 0; o >>= 1) v += __shfl_xor_sync(0xffffffffu, v, o);
    return v;
}
__device__ __forceinline__ void wsum2(float& a, float& b){
#pragma unroll
    for (int o = 16; o > 0; o >>= 1){
        a += __shfl_xor_sync(0xffffffffu, a, o);
        b += __shfl_xor_sync(0xffffffffu, b, o);
    }
}
__device__ __forceinline__ void wsum4(float& a, float& b, float& c, float& d){
#pragma unroll
    for (int o = 16; o > 0; o >>= 1){
        a += __shfl_xor_sync(0xffffffffu, a, o);
        b += __shfl_xor_sync(0xffffffffu, b, o);
        c += __shfl_xor_sync(0xffffffffu, c, o);
        d += __shfl_xor_sync(0xffffffffu, d, o);
    }
}

__device__ __forceinline__ void st_tag2(float2* p, float v, unsigned tag){
    asm volatile("st.global.v2.b32 [%0], {%1,%2};" :: "l"(p),
                 "r"(__float_as_uint(v)), "r"(tag) : "memory");
}
__device__ __forceinline__ void st_tag4(float4* p, float re, float im, unsigned tag){
    asm volatile("st.global.v4.b32 [%0], {%1,%2,%3,%4};" :: "l"(p),
                 "r"(__float_as_uint(re)), "r"(__float_as_uint(im)), "r"(tag), "r"(0u)
                 : "memory");
}
template<int N>
__device__ __forceinline__ void pollT(const float2* p, int stride, float* dst, unsigned tag){
    unsigned vx[N], vy[N];
#pragma unroll
    for (int i = 0; i < N; i++) vy[i] = tag + 1u;
    bool bad = true;
    while (bad){
        bad = false;
#pragma unroll
        for (int i = 0; i < N; i++){
            if (vy[i] != tag){
                asm volatile("ld.volatile.global.v2.b32 {%0,%1}, [%2];"
                             : "=r"(vx[i]), "=r"(vy[i]) : "l"(p + i*stride));
                if (vy[i] != tag) bad = true;
            }
        }
    }
#pragma unroll
    for (int i = 0; i < N; i++) dst[i] = __uint_as_float(vx[i]);
}
__device__ __forceinline__ float poll1(const float2* p, unsigned tag){
    unsigned vx, vy;
    do { asm volatile("ld.volatile.global.v2.b32 {%0,%1}, [%2];" : "=r"(vx), "=r"(vy) : "l"(p)); }
    while (vy != tag);
    return __uint_as_float(vx);
}

__global__ void __launch_bounds__(NTHR, 1) dtln_kernel(
    const float* __restrict__ mag,   const float* __restrict__ phase,
    const float* __restrict__ st1,   const float* __restrict__ st2,
    const float* __restrict__ wih10, const float* __restrict__ whh10,
    const float* __restrict__ bih10, const float* __restrict__ bhh10,
    const float* __restrict__ wih11, const float* __restrict__ whh11,
    const float* __restrict__ bih11, const float* __restrict__ bhh11,
    const float* __restrict__ d1w,   const float* __restrict__ d1b,
    const float* __restrict__ encw,  const float* __restrict__ gamma_,
    const float* __restrict__ beta_,
    const float* __restrict__ wih20, const float* __restrict__ whh20,
    const float* __restrict__ bih20, const float* __restrict__ bhh20,
    const float* __restrict__ wih21, const float* __restrict__ whh21,
    const float* __restrict__ bih21, const float* __restrict__ bhh21,
    const float* __restrict__ d2w,   const float* __restrict__ d2b,
    const float* __restrict__ decw,
    float* __restrict__ out)
{
    extern __shared__ char dsm[];
    const int tid  = threadIdx.x;
    const int lane = tid & 31;
    const int wid  = tid >> 5;
    const int cta  = blockIdx.x;
    const int gw   = cta * 8 + wid;        // 0..1023

    const unsigned TAG = *((volatile unsigned*)&g_epoch) + 1u;

    float* estS = (float*)(dsm + OFF_EST);

    if (cta < 16){
        // ================= A: LSTM1 layer0 =================
        int j = gw;
        float wiA[4][17], whA[4][4], bA[4], xrA[17], hrA[4];
#pragma unroll
        for (int g = 0; g < 4; g++){
            const float* w = wih10 + (size_t)(g*HID + j)*BINS;
#pragma unroll
            for (int i = 0; i < 17; i++){ int k = lane + 32*i; wiA[g][i] = (k < BINS) ? w[k] : 0.f; }
            const float* wh = whh10 + (size_t)(g*HID + j)*HID;
#pragma unroll
            for (int i = 0; i < 4; i++) whA[g][i] = wh[lane + 32*i];
            bA[g] = bih10[g*HID + j] + bhh10[g*HID + j];
        }
#pragma unroll
        for (int i = 0; i < 17; i++){ int k = lane + 32*i; xrA[i] = (k < BINS) ? mag[k] : 0.f; }
#pragma unroll
        for (int i = 0; i < 4; i++) hrA[i] = st1[lane + 32*i];
        float cprev = st1[2*HID + j];

        float a0=0.f,a1=0.f,a2=0.f,a3=0.f;
#pragma unroll
        for (int i = 0; i < 17; i++){
            float x = xrA[i];
            a0 = fmaf(wiA[0][i], x, a0); a1 = fmaf(wiA[1][i], x, a1);
            a2 = fmaf(wiA[2][i], x, a2); a3 = fmaf(wiA[3][i], x, a3);
        }
#pragma unroll
        for (int i = 0; i < 4; i++){
            float h = hrA[i];
            a0 = fmaf(whA[0][i], h, a0); a1 = fmaf(whA[1][i], h, a1);
            a2 = fmaf(whA[2][i], h, a2); a3 = fmaf(whA[3][i], h, a3);
        }
        wsum4(a0,a1,a2,a3);
        if (lane == 0){
            float c2 = sigm(a1+bA[1])*cprev + sigm(a0+bA[0])*tanhf(a2+bA[2]);
            float h2 = sigm(a3+bA[3])*tanhf(c2);
            out[WIN + j] = h2; out[WIN + 2*HID + j] = c2;
            st_tag2(&g_h1t[j], h2, TAG);
        }
    }
    else if (cta < 32){
        // ================= B: LSTM1 layer1 =================
        int j = gw - 128;
        float4 wi[4], wh[4]; float b[4];
#pragma unroll
        for (int g = 0; g < 4; g++){
            wi[g] = *(const float4*)(wih11 + (size_t)(g*HID + j)*HID + lane*4);
            wh[g] = *(const float4*)(whh11 + (size_t)(g*HID + j)*HID + lane*4);
            b[g]  = bih11[g*HID + j] + bhh11[g*HID + j];
        }
        float4 hr = *(const float4*)(st1 + HID + lane*4);
        float cprev = st1[3*HID + j];
        float x[4];
        pollT<4>(g_h1t + lane*4, 1, x, TAG);          // BLOCKED
        float a0 = wi[0].x*x[0]+wi[0].y*x[1]+wi[0].z*x[2]+wi[0].w*x[3] + wh[0].x*hr.x+wh[0].y*hr.y+wh[0].z*hr.z+wh[0].w*hr.w;
        float a1 = wi[1].x*x[0]+wi[1].y*x[1]+wi[1].z*x[2]+wi[1].w*x[3] + wh[1].x*hr.x+wh[1].y*hr.y+wh[1].z*hr.z+wh[1].w*hr.w;
        float a2 = wi[2].x*x[0]+wi[2].y*x[1]+wi[2].z*x[2]+wi[2].w*x[3] + wh[2].x*hr.x+wh[2].y*hr.y+wh[2].z*hr.z+wh[2].w*hr.w;
        float a3 = wi[3].x*x[0]+wi[3].y*x[1]+wi[3].z*x[2]+wi[3].w*x[3] + wh[3].x*hr.x+wh[3].y*hr.y+wh[3].z*hr.z+wh[3].w*hr.w;
        wsum4(a0,a1,a2,a3);
        if (lane == 0){
            float c2 = sigm(a1+b[1])*cprev + sigm(a0+b[0])*tanhf(a2+b[2]);
            float h2 = sigm(a3+b[3])*tanhf(c2);
            out[WIN + HID + j] = h2; out[WIN + 3*HID + j] = c2;
            st_tag2(&g_h2t[j], h2, TAG);
        }
    }
    else if (cta < 48){
        // ================= C: sum encP + norm + LSTM2 layer0 =================
        int j = (cta-32)*8 + wid;
        float4 wi0[4], wi1[4], wh[4]; float b[4];
#pragma unroll
        for (int g = 0; g < 4; g++){
            wi0[g] = *(const float4*)(wih20 + (size_t)(g*HID + j)*ENCN + lane*8);
            wi1[g] = *(const float4*)(wih20 + (size_t)(g*HID + j)*ENCN + lane*8 + 4);
            wh[g]  = *(const float4*)(whh20 + (size_t)(g*HID + j)*HID + lane*4);
            b[g]   = bih20[g*HID + j] + bhh20[g*HID + j];
        }
        float4 hr = *(const float4*)(st2 + lane*4);
        float cprev = st2[2*HID + j];
        float gamv = gamma_[tid], betv = beta_[tid];

        float v = 0.f;
#pragma unroll
        for (int c = 0; c < 4; c++){
            float pv[8];
            pollT<8>(g_encPt + (c*8)*ENCN + tid, ENCN, pv, TAG);
#pragma unroll
            for (int s = 0; s < 8; s++) v += pv[s];
        }
        if (cta == 32) st_tag2(&g_enct[tid], v, TAG);

        float sv = v, sq = v*v;
        wsum2(sv, sq);
        float* red  = (float*)(dsm + OFF_RED);
        float* red2 = (float*)(dsm + OFF_RED2);
        if (lane == 0){ red[wid] = sv; red2[wid] = sq; }
        __syncthreads();
        float tot = 0.f, tot2 = 0.f;
#pragma unroll
        for (int i = 0; i < 8; i++){ tot += red[i]; tot2 += red2[i]; }
        float mean = tot * (1.0f/ENCN);
        float var  = tot2 * (1.0f/ENCN) - mean*mean;
        float rstd = rsqrtf(var + 1e-7f);
        float* encn = (float*)(dsm + OFF_ENCN);
        encn[tid] = (v - mean) * rstd * gamv + betv;
        __syncthreads();

        float4 x0 = *(const float4*)&encn[lane*8];
        float4 x1 = *(const float4*)&encn[lane*8 + 4];
        float a0 = wi0[0].x*x0.x+wi0[0].y*x0.y+wi0[0].z*x0.z+wi0[0].w*x0.w + wi1[0].x*x1.x+wi1[0].y*x1.y+wi1[0].z*x1.z+wi1[0].w*x1.w
                 + wh[0].x*hr.x+wh[0].y*hr.y+wh[0].z*hr.z+wh[0].w*hr.w;
        float a1 = wi0[1].x*x0.x+wi0[1].y*x0.y+wi0[1].z*x0.z+wi0[1].w*x0.w + wi1[1].x*x1.x+wi1[1].y*x1.y+wi1[1].z*x1.z+wi1[1].w*x1.w
                 + wh[1].x*hr.x+wh[1].y*hr.y+wh[1].z*hr.z+wh[1].w*hr.w;
        float a2 = wi0[2].x*x0.x+wi0[2].y*x0.y+wi0[2].z*x0.z+wi0[2].w*x0.w + wi1[2].x*x1.x+wi1[2].y*x1.y+wi1[2].z*x1.z+wi1[2].w*x1.w
                 + wh[2].x*hr.x+wh[2].y*hr.y+wh[2].z*hr.z+wh[2].w*hr.w;
        float a3 = wi0[3].x*x0.x+wi0[3].y*x0.y+wi0[3].z*x0.z+wi0[3].w*x0.w + wi1[3].x*x1.x+wi1[3].y*x1.y+wi1[3].z*x1.z+wi1[3].w*x1.w
                 + wh[3].x*hr.x+wh[3].y*hr.y+wh[3].z*hr.z+wh[3].w*hr.w;
        wsum4(a0,a1,a2,a3);
        if (lane == 0){
            float c2 = sigm(a1+b[1])*cprev + sigm(a0+b[0])*tanhf(a2+b[2]);
            float h2 = sigm(a3+b[3])*tanhf(c2);
            out[WIN + 4*HID + j] = h2; out[WIN + 6*HID + j] = c2;
            st_tag2(&g_h1bt[j], h2, TAG);
        }
    }
    else if (cta < 64){
        // ================= D: LSTM2 layer1 + dense2 partials =================
        int dcta = cta - 48;               // 0..15
        int j0   = dcta*8;
        int j    = j0 + wid;
        float4 wi[4], wh[4]; float b[4];
#pragma unroll
        for (int g = 0; g < 4; g++){
            wi[g] = *(const float4*)(wih21 + (size_t)(g*HID + j)*HID + lane*4);
            wh[g] = *(const float4*)(whh21 + (size_t)(g*HID + j)*HID + lane*4);
            b[g]  = bih21[g*HID + j] + bhh21[g*HID + j];
        }
        float4 hr = *(const float4*)(st2 + HID + lane*4);
        float cprev = st2[3*HID + j];
        // d2w slice preload: thread tid owns row e=tid, columns j0..j0+7
        float pd[8];
#pragma unroll
        for (int c = 0; c < 8; c++) pd[c] = d2w[(size_t)tid*HID + j0 + c];

        float x[4];
        pollT<4>(g_h1bt + lane*4, 1, x, TAG);         // BLOCKED
        float a0 = wi[0].x*x[0]+wi[0].y*x[1]+wi[0].z*x[2]+wi[0].w*x[3] + wh[0].x*hr.x+wh[0].y*hr.y+wh[0].z*hr.z+wh[0].w*hr.w;
        float a1 = wi[1].x*x[0]+wi[1].y*x[1]+wi[1].z*x[2]+wi[1].w*x[3] + wh[1].x*hr.x+wh[1].y*hr.y+wh[1].z*hr.z+wh[1].w*hr.w;
        float a2 = wi[2].x*x[0]+wi[2].y*x[1]+wi[2].z*x[2]+wi[2].w*x[3] + wh[2].x*hr.x+wh[2].y*hr.y+wh[2].z*hr.z+wh[2].w*hr.w;
        float a3 = wi[3].x*x[0]+wi[3].y*x[1]+wi[3].z*x[2]+wi[3].w*x[3] + wh[3].x*hr.x+wh[3].y*hr.y+wh[3].z*hr.z+wh[3].w*hr.w;
        wsum4(a0,a1,a2,a3);
        float* h2loc = (float*)(dsm + OFF_H2LOC);
        if (lane == 0){
            float c2 = sigm(a1+b[1])*cprev + sigm(a0+b[0])*tanhf(a2+b[2]);
            float h2 = sigm(a3+b[3])*tanhf(c2);
            out[WIN + 5*HID + j] = h2; out[WIN + 7*HID + j] = c2;
            h2loc[wid] = h2;
        }
        __syncthreads();
        {
            float p = 0.f;
#pragma unroll
            for (int c = 0; c < 8; c++) p = fmaf(pd[c], h2loc[c], p);
            st_tag2(&g_d2Pt[dcta*ENCN + tid], p, TAG);
        }
    }
    else if (cta < 96){
        // ================= E: dense1 -> spectrum =================
        int ew = (cta-64)*8 + wid;         // 0..255
        int r0 = 2*ew;
        float4 wD0 = *(const float4*)(d1w + (size_t)(r0+0)*HID + lane*4);
        float4 wD1 = *(const float4*)(d1w + (size_t)(r0+1)*HID + lane*4);
        float b0 = d1b[r0+0], b1 = d1b[r0+1];
        float m0 = mag[r0+0], m1 = mag[r0+1];
        float c0,s0,c1,s1;
        sincosf(phase[r0+0], &s0, &c0);  sincosf(phase[r0+1], &s1, &c1);
        float4 w512 = make_float4(0.f,0.f,0.f,0.f);
        float b5=0.f, m5=0.f, c5=1.f, s5=0.f;
        if (ew == 0){
            w512 = *(const float4*)(d1w + (size_t)512*HID + lane*4);
            b5 = d1b[512]; m5 = mag[512];
            sincosf(phase[512], &s5, &c5);
        }
        float x[4];
        pollT<4>(g_h2t + lane*4, 1, x, TAG);          // BLOCKED
        float a0 = wD0.x*x[0]+wD0.y*x[1]+wD0.z*x[2]+wD0.w*x[3];
        float a1 = wD1.x*x[0]+wD1.y*x[1]+wD1.z*x[2]+wD1.w*x[3];
        float a5 = (ew == 0) ? (w512.x*x[0]+w512.y*x[1]+w512.z*x[2]+w512.w*x[3]) : 0.f;
        wsum2(a0, a1);
        a5 = wsum(a5);
        if (lane == 0){
            float e0 = sigm(a0+b0)*m0, e1 = sigm(a1+b1)*m1;
            st_tag4(&g_spect[r0],   e0*c0, e0*s0, TAG);
            st_tag4(&g_spect[r0+1], e1*c1, e1*s1, TAG);
            if (ew == 0){
                float e5 = sigm(a5+b5)*m5;
                st_tag4(&g_spect[512], e5*c5, e5*s5, TAG);
            }
        }
    }
    else {
        // ================= F: iDFT (recurrence) + partial encoder =================
        int fw = (cta-96)*8 + wid;         // 0..255
        int n_base = (cta-96)*32;
        float* encwT = (float*)(dsm + OFF_ENCWT);   // [nl*257 + e]
        float* y1s   = (float*)(dsm + OFF_Y1S);
        for (int i = tid; i < 256*32; i += NTHR){
            int e = i >> 5, nl = i & 31;
            encwT[nl*257 + e] = encw[(size_t)e*WIN + n_base + nl];
        }

        // angle-init BEFORE the wait (independent of spectrum)
        int n0 = fw*4;
        float cc[4], ss[4], cd[4], sd[4], acc[4];
#pragma unroll
        for (int q = 0; q < 4; q++){
            int n = n0 + q;
            int m0i = ((1+lane)*n) & (WIN-1);
            int mdi = (32*n) & (WIN-1);
            float sA, cA, sD, cD;
            sincospif((float)m0i * (1.0f/512.0f), &sA, &cA);
            sincospif((float)mdi * (1.0f/512.0f), &sD, &cD);
            cc[q] = cA; ss[q] = sA; cd[q] = cD; sd[q] = sD;
            acc[q] = 0.f;
        }

        // tagged spectrum poll: 16 v4 loads/lane, miss-mask retry
        float srv[16], siv[16];
        {
            unsigned miss = 0xFFFFu;
            while (miss){
#pragma unroll
                for (int t = 0; t < 16; t++){
                    if (miss & (1u << t)){
                        unsigned a,b2,c2,d2;
                        asm volatile("ld.volatile.global.v4.b32 {%0,%1,%2,%3}, [%4];"
                                     : "=r"(a), "=r"(b2), "=r"(c2), "=r"(d2)
                                     : "l"(&g_spect[1 + lane + 32*t]));
                        if (c2 == TAG){
                            srv[t] = __uint_as_float(a);
                            siv[t] = __uint_as_float(b2);
                            miss &= ~(1u << t);
                        }
                    }
                }
            }
        }
        float dcl = 0.f;
        if (lane == 0){
            unsigned a,b2,c2,d2;
            do {
                asm volatile("ld.volatile.global.v4.b32 {%0,%1,%2,%3}, [%4];"
                             : "=r"(a), "=r"(b2), "=r"(c2), "=r"(d2) : "l"(&g_spect[0]));
            } while (c2 != TAG);
            dcl = __uint_as_float(a);
        }
        float dc  = __shfl_sync(0xffffffffu, dcl, 0);
        float nyq = __shfl_sync(0xffffffffu, srv[15], 31);   // bin 512 = lane31,t15

#pragma unroll
        for (int t = 0; t < 16; t++){
            int k = 1 + lane + 32*t;
            if (k < 512){
                float sr_ = srv[t], si_ = siv[t];
#pragma unroll
                for (int q = 0; q < 4; q++){
                    acc[q] = fmaf(sr_, cc[q], acc[q]);
                    acc[q] = fmaf(-si_, ss[q], acc[q]);
                    float cn = cc[q]*cd[q] - ss[q]*sd[q];
                    ss[q]    = ss[q]*cd[q] + cc[q]*sd[q];
                    cc[q]    = cn;
                }
            }
        }
        wsum4(acc[0],acc[1],acc[2],acc[3]);
        if (lane == 0){
#pragma unroll
            for (int q = 0; q < 4; q++){
                int n = n0 + q;
                float ny = (n & 1) ? -nyq : nyq;
                y1s[wid*4 + q] = (dc + 2.0f*acc[q] + ny) * (1.0f/1024.0f);
            }
        }
        __syncthreads();
        {
            float acc2 = 0.f;
#pragma unroll
            for (int nl = 0; nl < 32; nl++)
                acc2 = fmaf(encwT[nl*257 + tid], y1s[nl], acc2);
            st_tag2(&g_encPt[(cta-96)*ENCN + tid], acc2, TAG);   // self-publishing
        }
    }

    // ================= final: est (from dense2 partials) + decoder =================
    float4 dec0, dec1; float d2bv;
    {
        const float* wr = decw + (size_t)gw*ENCN;
        dec0 = *(const float4*)(wr + lane*8);
        dec1 = *(const float4*)(wr + lane*8 + 4);
        d2bv = d2b[tid];
    }
    {
        float pv[16];
        pollT<16>(g_d2Pt + tid, ENCN, pv, TAG);
        float s = 0.f;
#pragma unroll
        for (int i = 0; i < 16; i++) s += pv[i];
        float encv = poll1(&g_enct[tid], TAG);
        estS[tid] = sigm(s + d2bv) * encv;
    }
    __syncthreads();
    {
        const float4* est4 = (const float4*)estS;
        float4 e0 = est4[lane*2], e1 = est4[lane*2 + 1];
        float acc = dec0.x*e0.x + dec0.y*e0.y + dec0.z*e0.z + dec0.w*e0.w
                  + dec1.x*e1.x + dec1.y*e1.y + dec1.z*e1.z + dec1.w*e1.w;
        acc = wsum(acc);
        if (lane == 0) out[gw] = acc;
    }

    // epoch bump
    if (cta == 0 && tid == 0) g_epoch = TAG;
}

extern "C" void kernel_launch(void* const* d_in, const int* in_sizes, int n_in,
                              void* d_out, int out_size)
{
    (void)in_sizes; (void)n_in; (void)out_size;
    static int configured = 0;
    if (!configured){
        cudaFuncSetAttribute(dtln_kernel, cudaFuncAttributeMaxDynamicSharedMemorySize, SMEM_TOTAL);
        configured = 1;
    }
    dtln_kernel<<<NBLK, NTHR, SMEM_TOTAL>>>(
        (const float*)d_in[0],  (const float*)d_in[1],
        (const float*)d_in[2],  (const float*)d_in[3],
        (const float*)d_in[4],  (const float*)d_in[5],
        (const float*)d_in[6],  (const float*)d_in[7],
        (const float*)d_in[8],  (const float*)d_in[9],
        (const float*)d_in[10], (const float*)d_in[11],
        (const float*)d_in[12], (const float*)d_in[13],
        (const float*)d_in[14], (const float*)d_in[15],
        (const float*)d_in[16],
        (const float*)d_in[17], (const float*)d_in[18],
        (const float*)d_in[19], (const float*)d_in[20],
        (const float*)d_in[21], (const float*)d_in[22],
        (const float*)d_in[23], (const float*)d_in[24],
        (const float*)d_in[25], (const float*)d_in[26],
        (const float*)d_in[27],
        (float*)d_out);
}

// round 15
// speedup vs baseline: 1.0303x; 1.0303x over previous
#include <cuda_runtime.h>
#include <math.h>

#define NBLK 128
#define NTHR 256
#define HID  128
#define BINS 513
#define WIN  1024
#define ENCN 256

// ---------------- device scratch ----------------
__device__ __align__(16) float g_h1[HID], g_h2[HID], g_h1b[HID], g_h2b[HID];
__device__ __align__(16) float g_sr[BINS+3], g_si[BINS+3];
__device__ __align__(16) float g_y1[WIN];
__device__ __align__(16) float g_enc[ENCN], g_est[ENCN];
__device__ unsigned g_cnt[9*32];
#define CNT(i) (&g_cnt[(i)*32])

// ---------------- dynamic smem layout (bytes) ----------------
#define OFF_D2W   0
#define OFF_Y1S   135168
#define OFF_EST   135296
#define OFF_RED   136320
#define OFF_RED2  136352
#define OFF_ENCN  136384
#define SMEM_TOTAL 137408

__device__ __forceinline__ float sigm(float x){ return 1.0f/(1.0f+__expf(-x)); }

__device__ __forceinline__ float wsum(float v){
#pragma unroll
    for (int o = 16; o > 0; o >>= 1) v += __shfl_xor_sync(0xffffffffu, v, o);
    return v;
}
__device__ __forceinline__ void wsum2(float& a, float& b){
#pragma unroll
    for (int o = 16; o > 0; o >>= 1){
        a += __shfl_xor_sync(0xffffffffu, a, o);
        b += __shfl_xor_sync(0xffffffffu, b, o);
    }
}
__device__ __forceinline__ void wsum4(float& a, float& b, float& c, float& d){
#pragma unroll
    for (int o = 16; o > 0; o >>= 1){
        a += __shfl_xor_sync(0xffffffffu, a, o);
        b += __shfl_xor_sync(0xffffffffu, b, o);
        c += __shfl_xor_sync(0xffffffffu, c, o);
        d += __shfl_xor_sync(0xffffffffu, d, o);
    }
}

__device__ __forceinline__ void redrel(unsigned* p){
    asm volatile("red.release.gpu.global.add.u32 [%0], 1;" :: "l"(p) : "memory");
}
__device__ __forceinline__ unsigned ldacq(const unsigned* p){
    unsigned v;
    asm volatile("ld.acquire.gpu.global.u32 %0, [%1];" : "=r"(v) : "l"(p) : "memory");
    return v;
}
__device__ __forceinline__ void signalf(unsigned* c, int tid){
    __syncthreads();
    if (tid == 0){
        asm volatile("fence.acq_rel.gpu;" ::: "memory");
        redrel(c);
    }
}
__device__ __forceinline__ void waitf(unsigned* c, unsigned tgt, int tid){
    if (tid == 0){ while (ldacq(c) < tgt) {} }
    __syncthreads();
}

__global__ void __launch_bounds__(NTHR, 1) dtln_kernel(
    const float* __restrict__ mag,   const float* __restrict__ phase,
    const float* __restrict__ st1,   const float* __restrict__ st2,
    const float* __restrict__ wih10, const float* __restrict__ whh10,
    const float* __restrict__ bih10, const float* __restrict__ bhh10,
    const float* __restrict__ wih11, const float* __restrict__ whh11,
    const float* __restrict__ bih11, const float* __restrict__ bhh11,
    const float* __restrict__ d1w,   const float* __restrict__ d1b,
    const float* __restrict__ encw,  const float* __restrict__ gamma_,
    const float* __restrict__ beta_,
    const float* __restrict__ wih20, const float* __restrict__ whh20,
    const float* __restrict__ bih20, const float* __restrict__ bhh20,
    const float* __restrict__ wih21, const float* __restrict__ whh21,
    const float* __restrict__ bih21, const float* __restrict__ bhh21,
    const float* __restrict__ d2w,   const float* __restrict__ d2b,
    const float* __restrict__ decw,
    float* __restrict__ out)
{
    extern __shared__ char dsm[];
    const int tid  = threadIdx.x;
    const int lane = tid & 31;
    const int wid  = tid >> 5;
    const int cta  = blockIdx.x;
    const int gw   = cta * 8 + wid;

    float4* d2wP = (float4*)(dsm + OFF_D2W);
    float*  estS = (float*)(dsm + OFF_EST);

    #define FILL_D2W() do{ \
        const float4* s4 = (const float4*)d2w; \
        for (int i = tid; i < 256*32; i += NTHR){ int e = i >> 5, k4 = i & 31; d2wP[e*33 + k4] = s4[i]; } \
    }while(0)

    if (cta < 16){
        // ================= A: LSTM1 layer0 =================
        int j = gw;
        float wiA[4][17], whA[4][4], bA[4], xrA[17], hrA[4];
#pragma unroll
        for (int g = 0; g < 4; g++){
            const float* w = wih10 + (size_t)(g*HID + j)*BINS;
#pragma unroll
            for (int i = 0; i < 17; i++){ int k = lane + 32*i; wiA[g][i] = (k < BINS) ? w[k] : 0.f; }
            const float* wh = whh10 + (size_t)(g*HID + j)*HID;
#pragma unroll
            for (int i = 0; i < 4; i++) whA[g][i] = wh[lane + 32*i];
            bA[g] = bih10[g*HID + j] + bhh10[g*HID + j];
        }
#pragma unroll
        for (int i = 0; i < 17; i++){ int k = lane + 32*i; xrA[i] = (k < BINS) ? mag[k] : 0.f; }
#pragma unroll
        for (int i = 0; i < 4; i++) hrA[i] = st1[lane + 32*i];
        float cprev = st1[2*HID + j];

        float a0=0.f,a1=0.f,a2=0.f,a3=0.f;
#pragma unroll
        for (int i = 0; i < 17; i++){
            float x = xrA[i];
            a0 = fmaf(wiA[0][i], x, a0); a1 = fmaf(wiA[1][i], x, a1);
            a2 = fmaf(wiA[2][i], x, a2); a3 = fmaf(wiA[3][i], x, a3);
        }
#pragma unroll
        for (int i = 0; i < 4; i++){
            float h = hrA[i];
            a0 = fmaf(whA[0][i], h, a0); a1 = fmaf(whA[1][i], h, a1);
            a2 = fmaf(whA[2][i], h, a2); a3 = fmaf(whA[3][i], h, a3);
        }
        wsum4(a0,a1,a2,a3);
        if (lane == 0){
            float c2 = sigm(a1+bA[1])*cprev + sigm(a0+bA[0])*tanhf(a2+bA[2]);
            float h2 = sigm(a3+bA[3])*tanhf(c2);
            out[WIN + j] = h2; out[WIN + 2*HID + j] = c2;
            g_h1[j] = h2;
        }
        signalf(CNT(0), tid);
        FILL_D2W();
    }
    else if (cta < 32){
        // ================= B: LSTM1 layer1 =================
        int j = gw - 128;
        float4 wi[4]; float pre[4];
        float4 hr = *(const float4*)(st1 + HID + lane*4);
#pragma unroll
        for (int g = 0; g < 4; g++){
            wi[g] = *(const float4*)(wih11 + (size_t)(g*HID + j)*HID + lane*4);
            float4 wh = *(const float4*)(whh11 + (size_t)(g*HID + j)*HID + lane*4);
            pre[g] = wh.x*hr.x + wh.y*hr.y + wh.z*hr.z + wh.w*hr.w;
        }
        float b0v = bih11[0*HID+j]+bhh11[0*HID+j], b1v = bih11[1*HID+j]+bhh11[1*HID+j];
        float b2v = bih11[2*HID+j]+bhh11[2*HID+j], b3v = bih11[3*HID+j]+bhh11[3*HID+j];
        float cprev = st1[3*HID + j];
        FILL_D2W();
        waitf(CNT(0), 16, tid);
        float4 x = __ldcg((const float4*)&g_h1[lane*4]);
        float a0 = fmaf(wi[0].x,x.x, fmaf(wi[0].y,x.y, fmaf(wi[0].z,x.z, fmaf(wi[0].w,x.w, pre[0]))));
        float a1 = fmaf(wi[1].x,x.x, fmaf(wi[1].y,x.y, fmaf(wi[1].z,x.z, fmaf(wi[1].w,x.w, pre[1]))));
        float a2 = fmaf(wi[2].x,x.x, fmaf(wi[2].y,x.y, fmaf(wi[2].z,x.z, fmaf(wi[2].w,x.w, pre[2]))));
        float a3 = fmaf(wi[3].x,x.x, fmaf(wi[3].y,x.y, fmaf(wi[3].z,x.z, fmaf(wi[3].w,x.w, pre[3]))));
        wsum4(a0,a1,a2,a3);
        if (lane == 0){
            float c2 = sigm(a1+b1v)*cprev + sigm(a0+b0v)*tanhf(a2+b2v);
            float h2 = sigm(a3+b3v)*tanhf(c2);
            out[WIN + HID + j] = h2; out[WIN + 3*HID + j] = c2;
            g_h2[j] = h2;
        }
        signalf(CNT(1), tid);
    }
    else if (cta < 48){
        // ================= C: instance-norm + LSTM2 layer0 =================
        int j = (cta-32)*8 + wid;
        float4 wi0[4], wi1[4]; float pre[4];
        float4 hr = *(const float4*)(st2 + lane*4);
#pragma unroll
        for (int g = 0; g < 4; g++){
            wi0[g] = *(const float4*)(wih20 + (size_t)(g*HID + j)*ENCN + lane*8);
            wi1[g] = *(const float4*)(wih20 + (size_t)(g*HID + j)*ENCN + lane*8 + 4);
            float4 wh = *(const float4*)(whh20 + (size_t)(g*HID + j)*HID + lane*4);
            pre[g] = wh.x*hr.x + wh.y*hr.y + wh.z*hr.z + wh.w*hr.w;
        }
        float b0v = bih20[0*HID+j]+bhh20[0*HID+j], b1v = bih20[1*HID+j]+bhh20[1*HID+j];
        float b2v = bih20[2*HID+j]+bhh20[2*HID+j], b3v = bih20[3*HID+j]+bhh20[3*HID+j];
        float cprev = st2[2*HID + j];
        float gamv = gamma_[tid], betv = beta_[tid];
        FILL_D2W();

        waitf(CNT(4), 32, tid);
        float v = __ldcg(&g_enc[tid]);
        float sv = v, sq = v*v;
        wsum2(sv, sq);
        float* red  = (float*)(dsm + OFF_RED);
        float* red2 = (float*)(dsm + OFF_RED2);
        if (lane == 0){ red[wid] = sv; red2[wid] = sq; }
        __syncthreads();
        float tot = 0.f, tot2 = 0.f;
#pragma unroll
        for (int i = 0; i < 8; i++){ tot += red[i]; tot2 += red2[i]; }
        float mean = tot * (1.0f/ENCN);
        float var  = tot2 * (1.0f/ENCN) - mean*mean;
        float rstd = rsqrtf(var + 1e-7f);
        float* encn = (float*)(dsm + OFF_ENCN);
        encn[tid] = (v - mean) * rstd * gamv + betv;
        __syncthreads();

        float4 x0 = *(const float4*)&encn[lane*8];
        float4 x1 = *(const float4*)&encn[lane*8 + 4];
        float a0 = wi0[0].x*x0.x+wi0[0].y*x0.y+wi0[0].z*x0.z+wi0[0].w*x0.w + wi1[0].x*x1.x+wi1[0].y*x1.y+wi1[0].z*x1.z+wi1[0].w*x1.w + pre[0];
        float a1 = wi0[1].x*x0.x+wi0[1].y*x0.y+wi0[1].z*x0.z+wi0[1].w*x0.w + wi1[1].x*x1.x+wi1[1].y*x1.y+wi1[1].z*x1.z+wi1[1].w*x1.w + pre[1];
        float a2 = wi0[2].x*x0.x+wi0[2].y*x0.y+wi0[2].z*x0.z+wi0[2].w*x0.w + wi1[2].x*x1.x+wi1[2].y*x1.y+wi1[2].z*x1.z+wi1[2].w*x1.w + pre[2];
        float a3 = wi0[3].x*x0.x+wi0[3].y*x0.y+wi0[3].z*x0.z+wi0[3].w*x0.w + wi1[3].x*x1.x+wi1[3].y*x1.y+wi1[3].z*x1.z+wi1[3].w*x1.w + pre[3];
        wsum4(a0,a1,a2,a3);
        if (lane == 0){
            float c2 = sigm(a1+b1v)*cprev + sigm(a0+b0v)*tanhf(a2+b2v);
            float h2 = sigm(a3+b3v)*tanhf(c2);
            out[WIN + 4*HID + j] = h2; out[WIN + 6*HID + j] = c2;
            g_h1b[j] = h2;
        }
        signalf(CNT(5), tid);
    }
    else if (cta < 64){
        // ================= D: LSTM2 layer1 =================
        int j = (cta-48)*8 + wid;
        float4 wi[4]; float pre[4];
        float4 hr = *(const float4*)(st2 + HID + lane*4);
#pragma unroll
        for (int g = 0; g < 4; g++){
            wi[g] = *(const float4*)(wih21 + (size_t)(g*HID + j)*HID + lane*4);
            float4 wh = *(const float4*)(whh21 + (size_t)(g*HID + j)*HID + lane*4);
            pre[g] = wh.x*hr.x + wh.y*hr.y + wh.z*hr.z + wh.w*hr.w;
        }
        float b0v = bih21[0*HID+j]+bhh21[0*HID+j], b1v = bih21[1*HID+j]+bhh21[1*HID+j];
        float b2v = bih21[2*HID+j]+bhh21[2*HID+j], b3v = bih21[3*HID+j]+bhh21[3*HID+j];
        float cprev = st2[3*HID + j];
        FILL_D2W();
        waitf(CNT(5), 16, tid);
        float4 x = __ldcg((const float4*)&g_h1b[lane*4]);
        float a0 = fmaf(wi[0].x,x.x, fmaf(wi[0].y,x.y, fmaf(wi[0].z,x.z, fmaf(wi[0].w,x.w, pre[0]))));
        float a1 = fmaf(wi[1].x,x.x, fmaf(wi[1].y,x.y, fmaf(wi[1].z,x.z, fmaf(wi[1].w,x.w, pre[1]))));
        float a2 = fmaf(wi[2].x,x.x, fmaf(wi[2].y,x.y, fmaf(wi[2].z,x.z, fmaf(wi[2].w,x.w, pre[2]))));
        float a3 = fmaf(wi[3].x,x.x, fmaf(wi[3].y,x.y, fmaf(wi[3].z,x.z, fmaf(wi[3].w,x.w, pre[3]))));
        wsum4(a0,a1,a2,a3);
        if (lane == 0){
            float c2 = sigm(a1+b1v)*cprev + sigm(a0+b0v)*tanhf(a2+b2v);
            float h2 = sigm(a3+b3v)*tanhf(c2);
            out[WIN + 5*HID + j] = h2; out[WIN + 7*HID + j] = c2;
            g_h2b[j] = h2;
        }
        signalf(CNT(6), tid);
    }
    else if (cta < 96){
        // ================= E: dense1->spectrum, dense2->est =================
        int ew = (cta-64)*8 + wid;
        int r0 = 2*ew;
        float4 wD0 = *(const float4*)(d1w + (size_t)(r0+0)*HID + lane*4);
        float4 wD1 = *(const float4*)(d1w + (size_t)(r0+1)*HID + lane*4);
        float b0 = d1b[r0+0], b1 = d1b[r0+1];
        float m0 = mag[r0+0], m1 = mag[r0+1];
        float c0,s0,c1,s1;
        sincosf(phase[r0+0], &s0, &c0);  sincosf(phase[r0+1], &s1, &c1);
        float4 w512 = make_float4(0.f,0.f,0.f,0.f);
        float b5=0.f, m5=0.f, c5=1.f, s5=0.f;
        if (ew == 0){
            w512 = *(const float4*)(d1w + (size_t)512*HID + lane*4);
            b5 = d1b[512]; m5 = mag[512];
            sincosf(phase[512], &s5, &c5);
        }
        float4 wF = *(const float4*)(d2w + (size_t)ew*HID + lane*4);
        float bF = d2b[ew];
        FILL_D2W();

        waitf(CNT(1), 16, tid);
        {
            float4 x = __ldcg((const float4*)&g_h2[lane*4]);
            float a0 = wD0.x*x.x+wD0.y*x.y+wD0.z*x.z+wD0.w*x.w;
            float a1 = wD1.x*x.x+wD1.y*x.y+wD1.z*x.z+wD1.w*x.w;
            wsum2(a0, a1);
            if (lane == 0){
                float e0 = sigm(a0+b0)*m0, e1 = sigm(a1+b1)*m1;
                g_sr[r0]   = e0*c0;  g_si[r0]   = e0*s0;
                g_sr[r0+1] = e1*c1;  g_si[r0+1] = e1*s1;
            }
            if (ew == 0){
                float a5 = w512.x*x.x+w512.y*x.y+w512.z*x.z+w512.w*x.w;
                a5 = wsum(a5);
                if (lane == 0){
                    float e5 = sigm(a5+b5)*m5;
                    g_sr[512] = e5*c5;  g_si[512] = e5*s5;
                }
            }
        }
        signalf(CNT(2), tid);

        waitf(CNT(6), 16, tid);
        {
            float4 x = __ldcg((const float4*)&g_h2b[lane*4]);
            float a = wF.x*x.x+wF.y*x.y+wF.z*x.z+wF.w*x.w;
            a = wsum(a);
            if (lane == 0){
                float encv = __ldcg(&g_enc[ew]);
                g_est[ew] = sigm(a+bF) * encv;
            }
        }
        signalf(CNT(7), tid);
    }
    else {
        // ================= F: iDFT (recurrence) then encoder =================
        int fw = (cta-96)*8 + wid;
        float4 wE[8];
        {
            const float* wr = encw + (size_t)fw*WIN;
#pragma unroll
            for (int c = 0; c < 8; c++) wE[c] = *(const float4*)(wr + c*128 + lane*4);
        }
        FILL_D2W();

        int n0 = fw*4;
        float cc[4], ss[4], cd[4], sd[4], acc[4];
#pragma unroll
        for (int q = 0; q < 4; q++){
            int n = n0 + q;
            int m0i = ((1+lane)*n) & (WIN-1);
            int mdi = (32*n) & (WIN-1);
            float sA, cA, sD, cD;
            sincospif((float)m0i * (1.0f/512.0f), &sA, &cA);
            sincospif((float)mdi * (1.0f/512.0f), &sD, &cD);
            cc[q] = cA; ss[q] = sA; cd[q] = cD; sd[q] = sD;
            acc[q] = 0.f;
        }

        waitf(CNT(2), 32, tid);
        {
            float dc  = __ldcg(&g_sr[0]);
            float nyq = __ldcg(&g_sr[512]);
            float srv[16], siv[16];
#pragma unroll
            for (int t = 0; t < 16; t++){
                int k = 1 + lane + 32*t;
                srv[t] = (k < 512) ? __ldcg(&g_sr[k]) : 0.f;
                siv[t] = (k < 512) ? __ldcg(&g_si[k]) : 0.f;
            }
#pragma unroll
            for (int t = 0; t < 16; t++){
                float sr_ = srv[t], si_ = siv[t];
#pragma unroll
                for (int q = 0; q < 4; q++){
                    acc[q] = fmaf(sr_, cc[q], acc[q]);
                    acc[q] = fmaf(-si_, ss[q], acc[q]);
                    float cn = cc[q]*cd[q] - ss[q]*sd[q];
                    ss[q]    = ss[q]*cd[q] + cc[q]*sd[q];
                    cc[q]    = cn;
                }
            }
            wsum4(acc[0],acc[1],acc[2],acc[3]);
            if (lane == 0){
#pragma unroll
                for (int q = 0; q < 4; q++){
                    int n = n0 + q;
                    float ny = (n & 1) ? -nyq : nyq;
                    g_y1[n] = (dc + 2.0f*acc[q] + ny) * (1.0f/1024.0f);
                }
            }
        }
        signalf(CNT(3), tid);

        waitf(CNT(3), 32, tid);
        {
            float acc2 = 0.f;
#pragma unroll
            for (int c = 0; c < 8; c++){
                float4 y = __ldcg((const float4*)&g_y1[c*128 + lane*4]);
                acc2 = fmaf(wE[c].x, y.x, acc2); acc2 = fmaf(wE[c].y, y.y, acc2);
                acc2 = fmaf(wE[c].z, y.z, acc2); acc2 = fmaf(wE[c].w, y.w, acc2);
            }
            acc2 = wsum(acc2);
            if (lane == 0) g_enc[fw] = acc2;
        }
        signalf(CNT(4), tid);
    }

    // ================= S9: est broadcast + decoder =================
    float4 dec0, dec1;
    {
        const float* wr = decw + (size_t)gw*ENCN;
        dec0 = *(const float4*)(wr + lane*8);
        dec1 = *(const float4*)(wr + lane*8 + 4);
    }
    waitf(CNT(7), 32, tid);
    {
        float4 e0 = __ldcg((const float4*)&g_est[lane*8]);
        float4 e1 = __ldcg((const float4*)&g_est[lane*8 + 4]);
        float acc = dec0.x*e0.x + dec0.y*e0.y + dec0.z*e0.z + dec0.w*e0.w
                  + dec1.x*e1.x + dec1.y*e1.y + dec1.z*e1.z + dec1.w*e1.w;
        acc = wsum(acc);
        if (lane == 0) out[gw] = acc;
    }

    // ================= done-count + counter reset =================
    __syncthreads();
    if (tid == 0) redrel(CNT(8));
    if (cta == 0 && tid == 0){
        while (ldacq(CNT(8)) < NBLK) {}
#pragma unroll
        for (int i = 0; i < 9; i++) *((volatile unsigned*)CNT(i)) = 0u;
    }
}

extern "C" void kernel_launch(void* const* d_in, const int* in_sizes, int n_in,
                              void* d_out, int out_size)
{
    (void)in_sizes; (void)n_in; (void)out_size;
    static int configured = 0;
    if (!configured){
        cudaFuncSetAttribute(dtln_kernel, cudaFuncAttributeMaxDynamicSharedMemorySize, SMEM_TOTAL);
        configured = 1;
    }
    dtln_kernel<<<NBLK, NTHR, SMEM_TOTAL>>>(
        (const float*)d_in[0],  (const float*)d_in[1],
        (const float*)d_in[2],  (const float*)d_in[3],
        (const float*)d_in[4],  (const float*)d_in[5],
        (const float*)d_in[6],  (const float*)d_in[7],
        (const float*)d_in[8],  (const float*)d_in[9],
        (const float*)d_in[10], (const float*)d_in[11],
        (const float*)d_in[12], (const float*)d_in[13],
        (const float*)d_in[14], (const float*)d_in[15],
        (const float*)d_in[16],
        (const float*)d_in[17], (const float*)d_in[18],
        (const float*)d_in[19], (const float*)d_in[20],
        (const float*)d_in[21], (const float*)d_in[22],
        (const float*)d_in[23], (const float*)d_in[24],
        (const float*)d_in[25], (const float*)d_in[26],
        (const float*)d_in[27],
        (float*)d_out);
}

// round 16
// speedup vs baseline: 1.1335x; 1.1001x over previous
#include <cuda_runtime.h>
#include <math.h>

#define NBLK 128
#define NTHR 256
#define HID  128
#define BINS 513
#define WIN  1024
#define ENCN 256

// ---------------- device scratch ----------------
__device__ __align__(16) float g_h1[HID], g_h2[HID], g_h1b[HID], g_h2b[HID];
__device__ __align__(16) float g_sr[BINS+3], g_si[BINS+3];
__device__ __align__(16) float g_encP[32*ENCN];     // partial enc rows
__device__ __align__(16) float g_enc[ENCN];
__device__ unsigned g_cnt[7*32];                    // counters, 128B apart
#define CNT(i) (&g_cnt[(i)*32])
// counters: 0:h1(16) 1:h2(16) 2:spec(32) 3:encP(32) 4:h1b(16) 5:h2b(16) 6:done(128)

// ---------------- dynamic smem layout (bytes) ----------------
#define OFF_D2W   0                   // 256 rows × 132 floats (pad 4) = 135168
#define OFF_ENCWT 135168              // 32 × 257 floats = 32896
#define OFF_Y1S   168064              // 32 floats
#define OFF_EST   168192              // 256 floats
#define OFF_H2B   169216              // 128 floats
#define OFF_RED   169728              // 8 floats
#define OFF_RED2  169760              // 8 floats
#define OFF_ENCN  169792              // 256 floats
#define SMEM_TOTAL 170816

__device__ __forceinline__ float sigm(float x){ return 1.0f/(1.0f+__expf(-x)); }

__device__ __forceinline__ float wsum(float v){
#pragma unroll
    for (int o = 16; o > 0; o >>= 1) v += __shfl_xor_sync(0xffffffffu, v, o);
    return v;
}
__device__ __forceinline__ void wsum2(float& a, float& b){
#pragma unroll
    for (int o = 16; o > 0; o >>= 1){
        a += __shfl_xor_sync(0xffffffffu, a, o);
        b += __shfl_xor_sync(0xffffffffu, b, o);
    }
}
__device__ __forceinline__ void wsum4(float& a, float& b, float& c, float& d){
#pragma unroll
    for (int o = 16; o > 0; o >>= 1){
        a += __shfl_xor_sync(0xffffffffu, a, o);
        b += __shfl_xor_sync(0xffffffffu, b, o);
        c += __shfl_xor_sync(0xffffffffu, c, o);
        d += __shfl_xor_sync(0xffffffffu, d, o);
    }
}

__device__ __forceinline__ void redrel(unsigned* p){
    asm volatile("red.release.gpu.global.add.u32 [%0], 1;" :: "l"(p) : "memory");
}
__device__ __forceinline__ unsigned ldacq(const unsigned* p){
    unsigned v;
    asm volatile("ld.acquire.gpu.global.u32 %0, [%1];" : "=r"(v) : "l"(p) : "memory");
    return v;
}
__device__ __forceinline__ void signalf(unsigned* c, int tid){
    __syncthreads();
    if (tid == 0){
        asm volatile("fence.acq_rel.gpu;" ::: "memory");
        redrel(c);
    }
}
__device__ __forceinline__ void waitf(unsigned* c, unsigned tgt, int tid){
    if (tid == 0){ while (ldacq(c) < tgt) {} }
    __syncthreads();
}

__global__ void __launch_bounds__(NTHR, 1) dtln_kernel(
    const float* __restrict__ mag,   const float* __restrict__ phase,
    const float* __restrict__ st1,   const float* __restrict__ st2,
    const float* __restrict__ wih10, const float* __restrict__ whh10,
    const float* __restrict__ bih10, const float* __restrict__ bhh10,
    const float* __restrict__ wih11, const float* __restrict__ whh11,
    const float* __restrict__ bih11, const float* __restrict__ bhh11,
    const float* __restrict__ d1w,   const float* __restrict__ d1b,
    const float* __restrict__ encw,  const float* __restrict__ gamma_,
    const float* __restrict__ beta_,
    const float* __restrict__ wih20, const float* __restrict__ whh20,
    const float* __restrict__ bih20, const float* __restrict__ bhh20,
    const float* __restrict__ wih21, const float* __restrict__ whh21,
    const float* __restrict__ bih21, const float* __restrict__ bhh21,
    const float* __restrict__ d2w,   const float* __restrict__ d2b,
    const float* __restrict__ decw,
    float* __restrict__ out)
{
    extern __shared__ char dsm[];
    const int tid  = threadIdx.x;
    const int lane = tid & 31;
    const int wid  = tid >> 5;
    const int cta  = blockIdx.x;
    const int gw   = cta * 8 + wid;        // 0..1023

    float4* d2wP   = (float4*)(dsm + OFF_D2W);     // [e*33 + k4]
    float*  estS   = (float*)(dsm + OFF_EST);
    float*  h2bS   = (float*)(dsm + OFF_H2B);

    // d2w smem fill: float4 i -> e=i>>5, k4=i&31 ; store at e*33+k4 (pad kills conflicts)
    #define FILL_D2W() do{ \
        const float4* s4 = (const float4*)d2w; \
        for (int i = tid; i < 256*32; i += NTHR){ int e = i >> 5, k4 = i & 31; d2wP[e*33 + k4] = s4[i]; } \
    }while(0)

    float4 dec0, dec1; float d2bv, encv = 0.f;
    #define LOAD_DEC() do{ \
        const float* wr = decw + (size_t)gw*ENCN; \
        dec0 = *(const float4*)(wr + lane*8); \
        dec1 = *(const float4*)(wr + lane*8 + 4); \
        d2bv = d2b[tid]; \
    }while(0)

    if (cta < 16){
        // ================= A: LSTM1 layer0 (S1) =================
        int j = gw;
        float wiA[4][17], whA[4][4], bA[4], xrA[17], hrA[4];
#pragma unroll
        for (int g = 0; g < 4; g++){
            const float* w = wih10 + (size_t)(g*HID + j)*BINS;
#pragma unroll
            for (int i = 0; i < 17; i++){ int k = lane + 32*i; wiA[g][i] = (k < BINS) ? w[k] : 0.f; }
            const float* wh = whh10 + (size_t)(g*HID + j)*HID;
#pragma unroll
            for (int i = 0; i < 4; i++) whA[g][i] = wh[lane + 32*i];
            bA[g] = bih10[g*HID + j] + bhh10[g*HID + j];
        }
#pragma unroll
        for (int i = 0; i < 17; i++){ int k = lane + 32*i; xrA[i] = (k < BINS) ? mag[k] : 0.f; }
#pragma unroll
        for (int i = 0; i < 4; i++) hrA[i] = st1[lane + 32*i];
        float cprev = st1[2*HID + j];

        float a0=0.f,a1=0.f,a2=0.f,a3=0.f;
#pragma unroll
        for (int i = 0; i < 17; i++){
            float x = xrA[i];
            a0 = fmaf(wiA[0][i], x, a0); a1 = fmaf(wiA[1][i], x, a1);
            a2 = fmaf(wiA[2][i], x, a2); a3 = fmaf(wiA[3][i], x, a3);
        }
#pragma unroll
        for (int i = 0; i < 4; i++){
            float h = hrA[i];
            a0 = fmaf(whA[0][i], h, a0); a1 = fmaf(whA[1][i], h, a1);
            a2 = fmaf(whA[2][i], h, a2); a3 = fmaf(whA[3][i], h, a3);
        }
        wsum4(a0,a1,a2,a3);
        if (lane == 0){
            float c2 = sigm(a1+bA[1])*cprev + sigm(a0+bA[0])*tanhf(a2+bA[2]);
            float h2 = sigm(a3+bA[3])*tanhf(c2);
            out[WIN + j] = h2; out[WIN + 2*HID + j] = c2;
            g_h1[j] = h2;
        }
        signalf(CNT(0), tid);
        FILL_D2W(); LOAD_DEC();
    }
    else if (cta < 32){
        // ================= B: LSTM1 layer1 (S2) =================
        int j = gw - 128;
        float4 wi[4], wh[4]; float b[4];
#pragma unroll
        for (int g = 0; g < 4; g++){
            wi[g] = *(const float4*)(wih11 + (size_t)(g*HID + j)*HID + lane*4);
            wh[g] = *(const float4*)(whh11 + (size_t)(g*HID + j)*HID + lane*4);
            b[g]  = bih11[g*HID + j] + bhh11[g*HID + j];
        }
        float4 hr = *(const float4*)(st1 + HID + lane*4);
        float cprev = st1[3*HID + j];
        FILL_D2W(); LOAD_DEC();
        waitf(CNT(0), 16, tid);
        float4 x = __ldcg((const float4*)&g_h1[lane*4]);
        float a0 = wi[0].x*x.x+wi[0].y*x.y+wi[0].z*x.z+wi[0].w*x.w + wh[0].x*hr.x+wh[0].y*hr.y+wh[0].z*hr.z+wh[0].w*hr.w;
        float a1 = wi[1].x*x.x+wi[1].y*x.y+wi[1].z*x.z+wi[1].w*x.w + wh[1].x*hr.x+wh[1].y*hr.y+wh[1].z*hr.z+wh[1].w*hr.w;
        float a2 = wi[2].x*x.x+wi[2].y*x.y+wi[2].z*x.z+wi[2].w*x.w + wh[2].x*hr.x+wh[2].y*hr.y+wh[2].z*hr.z+wh[2].w*hr.w;
        float a3 = wi[3].x*x.x+wi[3].y*x.y+wi[3].z*x.z+wi[3].w*x.w + wh[3].x*hr.x+wh[3].y*hr.y+wh[3].z*hr.z+wh[3].w*hr.w;
        wsum4(a0,a1,a2,a3);
        if (lane == 0){
            float c2 = sigm(a1+b[1])*cprev + sigm(a0+b[0])*tanhf(a2+b[2]);
            float h2 = sigm(a3+b[3])*tanhf(c2);
            out[WIN + HID + j] = h2; out[WIN + 3*HID + j] = c2;
            g_h2[j] = h2;
        }
        signalf(CNT(1), tid);
    }
    else if (cta < 48){
        // ================= C: sum partials + norm (1-pass) + LSTM2 layer0 =================
        int j = (cta-32)*8 + wid;
        float4 wi0[4], wi1[4], wh[4]; float b[4];
#pragma unroll
        for (int g = 0; g < 4; g++){
            wi0[g] = *(const float4*)(wih20 + (size_t)(g*HID + j)*ENCN + lane*8);
            wi1[g] = *(const float4*)(wih20 + (size_t)(g*HID + j)*ENCN + lane*8 + 4);
            wh[g]  = *(const float4*)(whh20 + (size_t)(g*HID + j)*HID + lane*4);
            b[g]   = bih20[g*HID + j] + bhh20[g*HID + j];
        }
        float4 hr = *(const float4*)(st2 + lane*4);
        float cprev = st2[2*HID + j];
        float gamv = gamma_[tid], betv = beta_[tid];
        FILL_D2W(); LOAD_DEC();

        waitf(CNT(3), 32, tid);
        float v = 0.f;
#pragma unroll
        for (int s = 0; s < 32; s++) v += __ldcg(&g_encP[s*ENCN + tid]);
        if (cta == 32) *((float*)&g_enc[tid]) = v;     // covered by C4 fence

        // single-pass norm (one syncthreads)
        float sv = v, sq = v*v;
        wsum2(sv, sq);
        float* red  = (float*)(dsm + OFF_RED);
        float* red2 = (float*)(dsm + OFF_RED2);
        if (lane == 0){ red[wid] = sv; red2[wid] = sq; }
        __syncthreads();
        float tot = 0.f, tot2 = 0.f;
#pragma unroll
        for (int i = 0; i < 8; i++){ tot += red[i]; tot2 += red2[i]; }
        float mean = tot * (1.0f/ENCN);
        float var  = tot2 * (1.0f/ENCN) - mean*mean;
        float rstd = rsqrtf(var + 1e-7f);
        float* encn = (float*)(dsm + OFF_ENCN);
        encn[tid] = (v - mean) * rstd * gamv + betv;
        __syncthreads();

        float4 x0 = *(const float4*)&encn[lane*8];
        float4 x1 = *(const float4*)&encn[lane*8 + 4];
        float a0 = wi0[0].x*x0.x+wi0[0].y*x0.y+wi0[0].z*x0.z+wi0[0].w*x0.w + wi1[0].x*x1.x+wi1[0].y*x1.y+wi1[0].z*x1.z+wi1[0].w*x1.w
                 + wh[0].x*hr.x+wh[0].y*hr.y+wh[0].z*hr.z+wh[0].w*hr.w;
        float a1 = wi0[1].x*x0.x+wi0[1].y*x0.y+wi0[1].z*x0.z+wi0[1].w*x0.w + wi1[1].x*x1.x+wi1[1].y*x1.y+wi1[1].z*x1.z+wi1[1].w*x1.w
                 + wh[1].x*hr.x+wh[1].y*hr.y+wh[1].z*hr.z+wh[1].w*hr.w;
        float a2 = wi0[2].x*x0.x+wi0[2].y*x0.y+wi0[2].z*x0.z+wi0[2].w*x0.w + wi1[2].x*x1.x+wi1[2].y*x1.y+wi1[2].z*x1.z+wi1[2].w*x1.w
                 + wh[2].x*hr.x+wh[2].y*hr.y+wh[2].z*hr.z+wh[2].w*hr.w;
        float a3 = wi0[3].x*x0.x+wi0[3].y*x0.y+wi0[3].z*x0.z+wi0[3].w*x0.w + wi1[3].x*x1.x+wi1[3].y*x1.y+wi1[3].z*x1.z+wi1[3].w*x1.w
                 + wh[3].x*hr.x+wh[3].y*hr.y+wh[3].z*hr.z+wh[3].w*hr.w;
        wsum4(a0,a1,a2,a3);
        if (lane == 0){
            float c2 = sigm(a1+b[1])*cprev + sigm(a0+b[0])*tanhf(a2+b[2]);
            float h2 = sigm(a3+b[3])*tanhf(c2);
            out[WIN + 4*HID + j] = h2; out[WIN + 6*HID + j] = c2;
            g_h1b[j] = h2;
        }
        signalf(CNT(4), tid);
    }
    else if (cta < 64){
        // ================= D: LSTM2 layer1 =================
        int j = (cta-48)*8 + wid;
        float4 wi[4], wh[4]; float b[4];
#pragma unroll
        for (int g = 0; g < 4; g++){
            wi[g] = *(const float4*)(wih21 + (size_t)(g*HID + j)*HID + lane*4);
            wh[g] = *(const float4*)(whh21 + (size_t)(g*HID + j)*HID + lane*4);
            b[g]  = bih21[g*HID + j] + bhh21[g*HID + j];
        }
        float4 hr = *(const float4*)(st2 + HID + lane*4);
        float cprev = st2[3*HID + j];
        FILL_D2W(); LOAD_DEC();
        waitf(CNT(4), 16, tid);
        float4 x = __ldcg((const float4*)&g_h1b[lane*4]);
        float a0 = wi[0].x*x.x+wi[0].y*x.y+wi[0].z*x.z+wi[0].w*x.w + wh[0].x*hr.x+wh[0].y*hr.y+wh[0].z*hr.z+wh[0].w*hr.w;
        float a1 = wi[1].x*x.x+wi[1].y*x.y+wi[1].z*x.z+wi[1].w*x.w + wh[1].x*hr.x+wh[1].y*hr.y+wh[1].z*hr.z+wh[1].w*hr.w;
        float a2 = wi[2].x*x.x+wi[2].y*x.y+wi[2].z*x.z+wi[2].w*x.w + wh[2].x*hr.x+wh[2].y*hr.y+wh[2].z*hr.z+wh[2].w*hr.w;
        float a3 = wi[3].x*x.x+wi[3].y*x.y+wi[3].z*x.z+wi[3].w*x.w + wh[3].x*hr.x+wh[3].y*hr.y+wh[3].z*hr.z+wh[3].w*hr.w;
        wsum4(a0,a1,a2,a3);
        if (lane == 0){
            float c2 = sigm(a1+b[1])*cprev + sigm(a0+b[0])*tanhf(a2+b[2]);
            float h2 = sigm(a3+b[3])*tanhf(c2);
            out[WIN + 5*HID + j] = h2; out[WIN + 7*HID + j] = c2;
            g_h2b[j] = h2;
        }
        signalf(CNT(5), tid);
    }
    else if (cta < 96){
        // ================= E: dense1 -> spectrum =================
        int ew = (cta-64)*8 + wid;         // 0..255
        int r0 = 2*ew;
        float4 wD0 = *(const float4*)(d1w + (size_t)(r0+0)*HID + lane*4);
        float4 wD1 = *(const float4*)(d1w + (size_t)(r0+1)*HID + lane*4);
        float b0 = d1b[r0+0], b1 = d1b[r0+1];
        float m0 = mag[r0+0], m1 = mag[r0+1];
        float c0,s0,c1,s1;
        sincosf(phase[r0+0], &s0, &c0);  sincosf(phase[r0+1], &s1, &c1);
        float4 w512 = make_float4(0.f,0.f,0.f,0.f);
        float b5=0.f, m5=0.f, c5=1.f, s5=0.f;
        if (ew == 0){
            w512 = *(const float4*)(d1w + (size_t)512*HID + lane*4);
            b5 = d1b[512]; m5 = mag[512];
            sincosf(phase[512], &s5, &c5);
        }
        FILL_D2W(); LOAD_DEC();

        waitf(CNT(1), 16, tid);
        float4 x = __ldcg((const float4*)&g_h2[lane*4]);
        float a0 = wD0.x*x.x+wD0.y*x.y+wD0.z*x.z+wD0.w*x.w;
        float a1 = wD1.x*x.x+wD1.y*x.y+wD1.z*x.z+wD1.w*x.w;
        wsum2(a0, a1);
        if (lane == 0){
            float e0 = sigm(a0+b0)*m0, e1 = sigm(a1+b1)*m1;
            g_sr[r0]   = e0*c0;  g_si[r0]   = e0*s0;
            g_sr[r0+1] = e1*c1;  g_si[r0+1] = e1*s1;
        }
        if (ew == 0){
            float a5 = w512.x*x.x+w512.y*x.y+w512.z*x.z+w512.w*x.w;
            a5 = wsum(a5);
            if (lane == 0){
                float e5 = sigm(a5+b5)*m5;
                g_sr[512] = e5*c5;  g_si[512] = e5*s5;
            }
        }
        signalf(CNT(2), tid);
    }
    else {
        // ================= F: iDFT (recurrence) + partial encoder =================
        int fw = (cta-96)*8 + wid;         // 0..255
        int n_base = (cta-96)*32;
        float* encwT = (float*)(dsm + OFF_ENCWT);   // [nl*257 + e]
        float* y1s   = (float*)(dsm + OFF_Y1S);
        for (int i = tid; i < 256*32; i += NTHR){
            int e = i >> 5, nl = i & 31;
            encwT[nl*257 + e] = encw[(size_t)e*WIN + n_base + nl];
        }
        FILL_D2W(); LOAD_DEC();

        waitf(CNT(2), 32, tid);
        {
            float dc  = __ldcg(&g_sr[0]);
            float nyq = __ldcg(&g_sr[512]);
            float srv[16], siv[16];
#pragma unroll
            for (int t = 0; t < 16; t++){
                int k = 1 + lane + 32*t;
                srv[t] = (k < 512) ? __ldcg(&g_sr[k]) : 0.f;
                siv[t] = (k < 512) ? __ldcg(&g_si[k]) : 0.f;
            }
            int n0 = fw*4;
            float cc[4], ss[4], cd[4], sd[4], acc[4];
#pragma unroll
            for (int q = 0; q < 4; q++){
                int n = n0 + q;
                int m0i = ((1+lane)*n) & (WIN-1);
                int mdi = (32*n) & (WIN-1);
                float sA, cA, sD, cD;
                sincospif((float)m0i * (1.0f/512.0f), &sA, &cA);
                sincospif((float)mdi * (1.0f/512.0f), &sD, &cD);
                cc[q] = cA; ss[q] = sA; cd[q] = cD; sd[q] = sD;
                acc[q] = 0.f;
            }
#pragma unroll
            for (int t = 0; t < 16; t++){
                float sr_ = srv[t], si_ = siv[t];
#pragma unroll
                for (int q = 0; q < 4; q++){
                    acc[q] = fmaf(sr_, cc[q], acc[q]);
                    acc[q] = fmaf(-si_, ss[q], acc[q]);
                    float cn = cc[q]*cd[q] - ss[q]*sd[q];
                    ss[q]    = ss[q]*cd[q] + cc[q]*sd[q];
                    cc[q]    = cn;
                }
            }
            wsum4(acc[0],acc[1],acc[2],acc[3]);
            if (lane == 0){
#pragma unroll
                for (int q = 0; q < 4; q++){
                    int n = n0 + q;
                    float ny = (n & 1) ? -nyq : nyq;
                    y1s[wid*4 + q] = (dc + 2.0f*acc[q] + ny) * (1.0f/1024.0f);
                }
            }
        }
        __syncthreads();
        {
            float acc = 0.f;
#pragma unroll
            for (int nl = 0; nl < 32; nl++)
                acc = fmaf(encwT[nl*257 + tid], y1s[nl], acc);
            g_encP[(cta-96)*ENCN + tid] = acc;
        }
        signalf(CNT(3), tid);
    }

    // ================= final: est (local) + decoder =================
    waitf(CNT(5), 16, tid);
    if (tid < HID) h2bS[tid] = __ldcg(&g_h2b[tid]);
    encv = __ldcg(&g_enc[tid]);
    __syncthreads();
    {
        const float4* h2b4 = (const float4*)h2bS;
        float acc = 0.f;
#pragma unroll
        for (int k4 = 0; k4 < 32; k4++){
            float4 w = d2wP[tid*33 + k4];
            float4 h = h2b4[k4];
            acc += w.x*h.x + w.y*h.y + w.z*h.z + w.w*h.w;
        }
        estS[tid] = sigm(acc + d2bv) * encv;
    }
    __syncthreads();
    {
        const float4* est4 = (const float4*)estS;
        float4 e0 = est4[lane*2], e1 = est4[lane*2 + 1];
        float acc = dec0.x*e0.x + dec0.y*e0.y + dec0.z*e0.z + dec0.w*e0.w
                  + dec1.x*e1.x + dec1.y*e1.y + dec1.z*e1.z + dec1.w*e1.w;
        acc = wsum(acc);
        if (lane == 0) out[gw] = acc;
    }

    // ================= done-count + counter reset =================
    __syncthreads();
    if (tid == 0) redrel(CNT(6));
    if (cta == 0 && tid == 0){
        while (ldacq(CNT(6)) < NBLK) {}
#pragma unroll
        for (int i = 0; i < 7; i++) *((volatile unsigned*)CNT(i)) = 0u;
    }
}

extern "C" void kernel_launch(void* const* d_in, const int* in_sizes, int n_in,
                              void* d_out, int out_size)
{
    (void)in_sizes; (void)n_in; (void)out_size;
    static int configured = 0;
    if (!configured){
        cudaFuncSetAttribute(dtln_kernel, cudaFuncAttributeMaxDynamicSharedMemorySize, SMEM_TOTAL);
        configured = 1;
    }
    dtln_kernel<<<NBLK, NTHR, SMEM_TOTAL>>>(
        (const float*)d_in[0],  (const float*)d_in[1],
        (const float*)d_in[2],  (const float*)d_in[3],
        (const float*)d_in[4],  (const float*)d_in[5],
        (const float*)d_in[6],  (const float*)d_in[7],
        (const float*)d_in[8],  (const float*)d_in[9],
        (const float*)d_in[10], (const float*)d_in[11],
        (const float*)d_in[12], (const float*)d_in[13],
        (const float*)d_in[14], (const float*)d_in[15],
        (const float*)d_in[16],
        (const float*)d_in[17], (const float*)d_in[18],
        (const float*)d_in[19], (const float*)d_in[20],
        (const float*)d_in[21], (const float*)d_in[22],
        (const float*)d_in[23], (const float*)d_in[24],
        (const float*)d_in[25], (const float*)d_in[26],
        (const float*)d_in[27],
        (float*)d_out);
}